// round 1
// baseline (speedup 1.0000x reference)
#include <cuda_runtime.h>

// Fused LSTM cell: g[b,g,h] = sum_k Z[b,k] * V[g,k,h]  (Z = [x | h_old], K=768)
// then elementwise gates + state update, writing h_new (out[0:BH]) and c_new (out[BH:2BH]).
//
// Tiling: BM=128 rows x BN=32 h-cols x all 4 gates per block, BK=32, 256 threads,
// per-thread micro-tile TM=8 x TN=2 x 4 gates = 64 accumulators.

#define BM 128
#define BN 32
#define BK 32
#define TM 8
#define TN 2
#define NTHREADS 256
#define ZS_STRIDE 132   // 128 + 4 pad, keeps 16B alignment per k-row

__global__ __launch_bounds__(NTHREADS, 2)
void lstm_fused_kernel(const float* __restrict__ x,
                       const float* __restrict__ h_old,
                       const float* __restrict__ c_old,
                       const float* __restrict__ U,
                       const float* __restrict__ bU,
                       const float* __restrict__ W,
                       const float* __restrict__ bW,
                       float* __restrict__ out,
                       int B)
{
    __shared__ float Zs[BK][ZS_STRIDE];   // Z tile transposed: [k][m]
    __shared__ float Vs[4][BK][BN];       // weight tile per gate: [g][k][n]

    const int tid = threadIdx.x;
    const int tx  = tid & 15;   // 0..15 -> N direction (x TN = 32 cols)
    const int ty  = tid >> 4;   // 0..15 -> M direction (x TM = 128 rows)
    const int m0  = blockIdx.y * BM;
    const int n0  = blockIdx.x * BN;

    float acc[4][TM][TN];
    #pragma unroll
    for (int g = 0; g < 4; g++)
        #pragma unroll
        for (int i = 0; i < TM; i++)
            #pragma unroll
            for (int j = 0; j < TN; j++)
                acc[g][i][j] = 0.0f;

    for (int kt = 0; kt < 768; kt += BK) {
        // ---- load Z tile (128 rows x 32 k), float4 along k, transposed store ----
        #pragma unroll
        for (int p = 0; p < 4; p++) {
            int e = p * 1024 + tid * 4;   // element within tile
            int m = e >> 5;               // row within tile (0..127)
            int k = e & 31;               // k within tile (multiple of 4)
            int kg = kt + k;
            float4 v;
            if (kg < 256) {
                v = *reinterpret_cast<const float4*>(&x[(size_t)(m0 + m) * 256 + kg]);
            } else {
                v = *reinterpret_cast<const float4*>(&h_old[(size_t)(m0 + m) * 512 + (kg - 256)]);
            }
            Zs[k + 0][m] = v.x;
            Zs[k + 1][m] = v.y;
            Zs[k + 2][m] = v.z;
            Zs[k + 3][m] = v.w;
        }

        // ---- load V tile (4 gates x 32 k x 32 n), float4 along n ----
        #pragma unroll
        for (int p = 0; p < 4; p++) {
            int e = p * 1024 + tid * 4;
            int n = e & 31;               // col within tile (multiple of 4)
            int r = e >> 5;               // (g,k) row: 0..127
            int g = r >> 5;
            int k = r & 31;
            int kg = kt + k;
            float4 v;
            if (kg < 256) {
                v = *reinterpret_cast<const float4*>(&U[((size_t)g * 256 + kg) * 512 + n0 + n]);
            } else {
                v = *reinterpret_cast<const float4*>(&W[((size_t)g * 512 + (kg - 256)) * 512 + n0 + n]);
            }
            *reinterpret_cast<float4*>(&Vs[g][k][n]) = v;
        }
        __syncthreads();

        // ---- compute ----
        #pragma unroll
        for (int k = 0; k < BK; k++) {
            float zr[TM];
            #pragma unroll
            for (int i = 0; i < TM; i++) zr[i] = Zs[k][ty * TM + i];
            float vr[4][TN];
            #pragma unroll
            for (int g = 0; g < 4; g++) {
                vr[g][0] = Vs[g][k][tx * TN + 0];
                vr[g][1] = Vs[g][k][tx * TN + 1];
            }
            #pragma unroll
            for (int g = 0; g < 4; g++)
                #pragma unroll
                for (int i = 0; i < TM; i++)
                    #pragma unroll
                    for (int j = 0; j < TN; j++)
                        acc[g][i][j] += zr[i] * vr[g][j];
        }
        __syncthreads();
    }

    // ---- epilogue: bias + activations + state update ----
    const size_t BH = (size_t)B * 512;
    #pragma unroll
    for (int j = 0; j < TN; j++) {
        int h = n0 + tx * TN + j;
        float b_i = bU[0 * 512 + h] + bW[0 * 512 + h];
        float b_f = bU[1 * 512 + h] + bW[1 * 512 + h];
        float b_o = bU[2 * 512 + h] + bW[2 * 512 + h];
        float b_c = bU[3 * 512 + h] + bW[3 * 512 + h];
        #pragma unroll
        for (int i = 0; i < TM; i++) {
            int m = m0 + ty * TM + i;
            float gi = acc[0][i][j] + b_i;
            float gf = acc[1][i][j] + b_f;
            float go = acc[2][i][j] + b_o;
            float gc = acc[3][i][j] + b_c;

            float it = 1.0f / (1.0f + __expf(-gi));
            float ft = 1.0f / (1.0f + __expf(-gf));
            float ot = 1.0f / (1.0f + __expf(-go));
            float ct = tanhf(gc);

            float cold = c_old[(size_t)m * 512 + h];
            float cn = it * ct + ft * cold;
            float hn = ot * tanhf(cn);

            out[(size_t)m * 512 + h]      = hn;   // h_new
            out[BH + (size_t)m * 512 + h] = cn;   // c_new
        }
    }
}

extern "C" void kernel_launch(void* const* d_in, const int* in_sizes, int n_in,
                              void* d_out, int out_size)
{
    const float* x     = (const float*)d_in[0];  // [B, 256]
    const float* h_old = (const float*)d_in[1];  // [B, 512]
    const float* c_old = (const float*)d_in[2];  // [B, 512]
    const float* U     = (const float*)d_in[3];  // [4, 256, 512]
    const float* bU    = (const float*)d_in[4];  // [4, 512]
    const float* W     = (const float*)d_in[5];  // [4, 512, 512]
    const float* bW    = (const float*)d_in[6];  // [4, 512]
    float* out = (float*)d_out;                  // [2, B, 512]: h_new then c_new

    int B = in_sizes[0] / 256;

    dim3 grid(512 / BN, B / BM);   // (16, 512)
    dim3 block(NTHREADS);
    lstm_fused_kernel<<<grid, block>>>(x, h_old, c_old, U, bU, W, bW, out, B);
}

// round 4
// speedup vs baseline: 1.6277x; 1.6277x over previous
#include <cuda_runtime.h>
#include <cuda_bf16.h>
#include <cstdint>

// ============================================================================
// Fused LSTM cell via mma.sync bf16 split-GEMM (no tcgen05 — plain sm_103 PTX).
//   g[b, n] = sum_k Z[b,k] * Vt[n,k],  Z = [x | h_old] (K=768),
//   n = (h<<2)|g interleaved gate-columns (2048 total).
//   Split: a = a_hi + a_lo (bf16); D += Ah*Bh + Ah*Bl + Al*Bh  (fp32 accum).
// ============================================================================

#define BM 256
#define BN 128
#define BK 64
#define NIT 12              // 768 / 64
#define NTHR 256

#define STAGE_BYTES 98304   // Ah 32K + Al 32K + Bh 16K + Bl 16K
#define SA_H 0
#define SA_L 32768
#define SB_H 65536
#define SB_L 81920
#define SM_TOTAL (2 * STAGE_BYTES)   // 192 KB
#define EPI_LD 132                   // padded f32 row stride for epilogue

__device__ __align__(16) __nv_bfloat16 g_Vhi[2048 * 768];
__device__ __align__(16) __nv_bfloat16 g_Vlo[2048 * 768];
__device__ __align__(16) __nv_bfloat16 g_Zhi[65536 * 768];
__device__ __align__(16) __nv_bfloat16 g_Zlo[65536 * 768];

// ---------------------------------------------------------------------------
__device__ __forceinline__ uint32_t smem_u32(const void* p) {
    uint32_t a;
    asm("{ .reg .u64 t; cvta.to.shared.u64 t, %1; cvt.u32.u64 %0, t; }" : "=r"(a) : "l"(p));
    return a;
}
__device__ __forceinline__ uint32_t swz(uint32_t off) { return off ^ ((off >> 3) & 0x70); }

__device__ __forceinline__ void cp16(uint32_t dst, const void* src) {
    asm volatile("cp.async.cg.shared.global [%0], [%1], 16;" :: "r"(dst), "l"(src) : "memory");
}
#define CP_COMMIT() asm volatile("cp.async.commit_group;" ::: "memory")
template <int N> __device__ __forceinline__ void cp_wait() {
    asm volatile("cp.async.wait_group %0;" :: "n"(N) : "memory");
}

__device__ __forceinline__ void ldm4(uint32_t r[4], uint32_t a) {
    asm volatile("ldmatrix.sync.aligned.m8n8.x4.shared.b16 {%0,%1,%2,%3}, [%4];"
        : "=r"(r[0]), "=r"(r[1]), "=r"(r[2]), "=r"(r[3]) : "r"(a));
}
__device__ __forceinline__ void mma16816(float d[4], const uint32_t a[4],
                                         uint32_t b0, uint32_t b1) {
    asm volatile(
        "mma.sync.aligned.m16n8k16.row.col.f32.bf16.bf16.f32 "
        "{%0,%1,%2,%3}, {%4,%5,%6,%7}, {%8,%9}, {%0,%1,%2,%3};"
        : "+f"(d[0]), "+f"(d[1]), "+f"(d[2]), "+f"(d[3])
        : "r"(a[0]), "r"(a[1]), "r"(a[2]), "r"(a[3]), "r"(b0), "r"(b1));
}

__device__ __forceinline__ float sigmoidf_(float x) {
    return 1.0f / (1.0f + __expf(-x));
}
__device__ __forceinline__ float tanhf_(float x) {
    return 2.0f / (1.0f + __expf(-2.0f * x)) - 1.0f;
}

// ---------------------------------------------------------------------------
// Prep 1: transpose + hi/lo split weights. Vt[n][k], n = (h<<2)|g.
// ---------------------------------------------------------------------------
__global__ void lstm_wprep(const float* __restrict__ U, const float* __restrict__ W) {
    int idx = blockIdx.x * blockDim.x + threadIdx.x;
    if (idx >= 2048 * 768) return;
    int n = idx / 768, kk = idx - n * 768;
    int g = n & 3, h = n >> 2;
    float v = (kk < 256) ? U[((size_t)g * 256 + kk) * 512 + h]
                         : W[((size_t)g * 512 + (kk - 256)) * 512 + h];
    __nv_bfloat16 hi = __float2bfloat16(v);
    g_Vhi[idx] = hi;
    g_Vlo[idx] = __float2bfloat16(v - __bfloat162float(hi));
}

// ---------------------------------------------------------------------------
// Prep 2: hi/lo split Z = [x | h_old] -> g_Zhi/g_Zlo [B][768].
// ---------------------------------------------------------------------------
__global__ void lstm_zprep(const float* __restrict__ x, const float* __restrict__ h_old) {
    int idx = blockIdx.x * blockDim.x + threadIdx.x;   // one float4 each
    int m = idx / 192;
    int k = (idx - m * 192) * 4;
    float4 v = (k < 256)
        ? *reinterpret_cast<const float4*>(x + (size_t)m * 256 + k)
        : *reinterpret_cast<const float4*>(h_old + (size_t)m * 512 + (k - 256));
    __nv_bfloat162 h01 = __float22bfloat162_rn(make_float2(v.x, v.y));
    __nv_bfloat162 h23 = __float22bfloat162_rn(make_float2(v.z, v.w));
    float2 f01 = __bfloat1622float2(h01);
    float2 f23 = __bfloat1622float2(h23);
    __nv_bfloat162 l01 = __float22bfloat162_rn(make_float2(v.x - f01.x, v.y - f01.y));
    __nv_bfloat162 l23 = __float22bfloat162_rn(make_float2(v.z - f23.x, v.w - f23.y));
    uint2 hp, lp;
    hp.x = *reinterpret_cast<uint32_t*>(&h01); hp.y = *reinterpret_cast<uint32_t*>(&h23);
    lp.x = *reinterpret_cast<uint32_t*>(&l01); lp.y = *reinterpret_cast<uint32_t*>(&l23);
    *reinterpret_cast<uint2*>(g_Zhi + (size_t)m * 768 + k) = hp;
    *reinterpret_cast<uint2*>(g_Zlo + (size_t)m * 768 + k) = lp;
}

// ---------------------------------------------------------------------------
// Stage fill: 24 cp.async x 16B per thread.
// ---------------------------------------------------------------------------
__device__ __forceinline__ void fill_stage(uint32_t sst, int it, int tid, int m0, int n0g) {
    const int kt2 = it * 128;   // byte offset within 1536-byte row
    // A hi/lo: thread t owns row t (8 chunks of 16B each)
    {
        const char* sh = (const char*)g_Zhi + (size_t)(m0 + tid) * 1536 + kt2;
        const char* sl = (const char*)g_Zlo + (size_t)(m0 + tid) * 1536 + kt2;
        #pragma unroll
        for (int c = 0; c < 8; c++) {
            uint32_t so = swz((uint32_t)(tid * 128 + c * 16));
            cp16(sst + SA_H + so, sh + c * 16);
            cp16(sst + SA_L + so, sl + c * 16);
        }
    }
    // B: threads 0-127 -> Bh rows, 128-255 -> Bl rows
    {
        const int n = tid & 127;
        const __nv_bfloat16* base = (tid & 128) ? g_Vlo : g_Vhi;
        const uint32_t db = sst + ((tid & 128) ? SB_L : SB_H);
        const char* src = (const char*)base + (size_t)(n0g + n) * 1536 + kt2;
        #pragma unroll
        for (int c = 0; c < 8; c++)
            cp16(db + swz((uint32_t)(n * 128 + c * 16)), src + c * 16);
    }
}

// ---------------------------------------------------------------------------
// Main GEMM + epilogue.
// ---------------------------------------------------------------------------
__global__ __launch_bounds__(NTHR, 1)
void lstm_mma_kernel(const float* __restrict__ c_old,
                     const float* __restrict__ bU,
                     const float* __restrict__ bW,
                     float* __restrict__ out,
                     int B)
{
    extern __shared__ char sm[];
    const uint32_t sb = smem_u32(sm);
    const int tid  = threadIdx.x;
    const int wid  = tid >> 5;
    const int lane = tid & 31;

    const int m0  = blockIdx.y * BM;
    const int n0g = blockIdx.x * BN;
    const int h0  = blockIdx.x * 32;

    const int wm = (wid >> 1) * 64;   // warp m offset in CTA tile
    const int wn = (wid & 1) * 64;    // warp n offset

    // per-lane ldmatrix row/k constants (byte units for k)
    const int a_row = lane & 15;
    const int a_kh  = (lane >> 4) * 16;
    const int b_row = (lane & 7) + ((lane & 16) >> 1);
    const int b_kh  = ((lane >> 3) & 1) * 16;

    float acc[4][8][4];
    #pragma unroll
    for (int mt = 0; mt < 4; mt++)
        #pragma unroll
        for (int nt = 0; nt < 8; nt++)
            #pragma unroll
            for (int r = 0; r < 4; r++) acc[mt][nt][r] = 0.0f;

    // ---- pipeline prologue ----
    fill_stage(sb, 0, tid, m0, n0g);               CP_COMMIT();
    fill_stage(sb + STAGE_BYTES, 1, tid, m0, n0g); CP_COMMIT();
    cp_wait<1>();
    __syncthreads();

    for (int it = 0; it < NIT; it++) {
        const uint32_t st = sb + (uint32_t)(it & 1) * STAGE_BYTES;

        #pragma unroll
        for (int ks = 0; ks < 4; ks++) {
            uint32_t ah[4][4], bb[4][4];
            const uint32_t kb = ks * 32;

            // product 1: Ah * Bh
            #pragma unroll
            for (int mt = 0; mt < 4; mt++)
                ldm4(ah[mt], st + SA_H + swz((uint32_t)((wm + mt * 16 + a_row) * 128 + kb + a_kh)));
            #pragma unroll
            for (int p = 0; p < 4; p++)
                ldm4(bb[p], st + SB_H + swz((uint32_t)((wn + p * 16 + b_row) * 128 + kb + b_kh)));
            #pragma unroll
            for (int mt = 0; mt < 4; mt++)
                #pragma unroll
                for (int nt = 0; nt < 8; nt++)
                    mma16816(acc[mt][nt], ah[mt], bb[nt >> 1][(nt & 1) * 2], bb[nt >> 1][(nt & 1) * 2 + 1]);

            // product 2: Ah * Bl
            #pragma unroll
            for (int p = 0; p < 4; p++)
                ldm4(bb[p], st + SB_L + swz((uint32_t)((wn + p * 16 + b_row) * 128 + kb + b_kh)));
            #pragma unroll
            for (int mt = 0; mt < 4; mt++)
                #pragma unroll
                for (int nt = 0; nt < 8; nt++)
                    mma16816(acc[mt][nt], ah[mt], bb[nt >> 1][(nt & 1) * 2], bb[nt >> 1][(nt & 1) * 2 + 1]);

            // product 3: Al * Bh
            #pragma unroll
            for (int mt = 0; mt < 4; mt++)
                ldm4(ah[mt], st + SA_L + swz((uint32_t)((wm + mt * 16 + a_row) * 128 + kb + a_kh)));
            #pragma unroll
            for (int p = 0; p < 4; p++)
                ldm4(bb[p], st + SB_H + swz((uint32_t)((wn + p * 16 + b_row) * 128 + kb + b_kh)));
            #pragma unroll
            for (int mt = 0; mt < 4; mt++)
                #pragma unroll
                for (int nt = 0; nt < 8; nt++)
                    mma16816(acc[mt][nt], ah[mt], bb[nt >> 1][(nt & 1) * 2], bb[nt >> 1][(nt & 1) * 2 + 1]);
        }

        __syncthreads();    // all warps done reading this stage
        if (it + 2 < NIT) {
            fill_stage(sb + (uint32_t)(it & 1) * STAGE_BYTES, it + 2, tid, m0, n0g);
            CP_COMMIT();
            cp_wait<1>();
        } else {
            cp_wait<0>();
        }
        __syncthreads();
    }

    // ---- epilogue: accums -> SMEM (row stride 132 f32) ----
    float* epi = reinterpret_cast<float*>(sm);
    #pragma unroll
    for (int mt = 0; mt < 4; mt++) {
        #pragma unroll
        for (int nt = 0; nt < 8; nt++) {
            const int m = wm + mt * 16 + (lane >> 2);
            const int n = wn + nt * 8 + (lane & 3) * 2;
            *reinterpret_cast<float2*>(&epi[m * EPI_LD + n]) =
                make_float2(acc[mt][nt][0], acc[mt][nt][1]);
            *reinterpret_cast<float2*>(&epi[(m + 8) * EPI_LD + n]) =
                make_float2(acc[mt][nt][2], acc[mt][nt][3]);
        }
    }
    __syncthreads();

    // ---- gates + state update, coalesced ----
    {
        const int h_loc = tid & 31;
        const int mrow0 = tid >> 5;
        const size_t BH = (size_t)B * 512;
        const float bi = bU[0 * 512 + h0 + h_loc] + bW[0 * 512 + h0 + h_loc];
        const float bf = bU[1 * 512 + h0 + h_loc] + bW[1 * 512 + h0 + h_loc];
        const float bo = bU[2 * 512 + h0 + h_loc] + bW[2 * 512 + h0 + h_loc];
        const float bc = bU[3 * 512 + h0 + h_loc] + bW[3 * 512 + h0 + h_loc];

        #pragma unroll 8
        for (int j = 0; j < 32; j++) {
            const int m = mrow0 + 8 * j;
            float4 gv = *reinterpret_cast<const float4*>(&epi[m * EPI_LD + h_loc * 4]);
            const float i_t = sigmoidf_(gv.x + bi);
            const float f_t = sigmoidf_(gv.y + bf);
            const float o_t = sigmoidf_(gv.z + bo);
            const float c_t = tanhf_(gv.w + bc);
            const size_t off = (size_t)(m0 + m) * 512 + h0 + h_loc;
            const float cn = i_t * c_t + f_t * c_old[off];
            out[off]      = o_t * tanhf_(cn);   // h_new
            out[BH + off] = cn;                 // c_new
        }
    }
}

// ---------------------------------------------------------------------------
extern "C" void kernel_launch(void* const* d_in, const int* in_sizes, int n_in,
                              void* d_out, int out_size)
{
    const float* x     = (const float*)d_in[0];  // [B, 256]
    const float* h_old = (const float*)d_in[1];  // [B, 512]
    const float* c_old = (const float*)d_in[2];  // [B, 512]
    const float* U     = (const float*)d_in[3];  // [4, 256, 512]
    const float* bU    = (const float*)d_in[4];  // [4, 512]
    const float* W     = (const float*)d_in[5];  // [4, 512, 512]
    const float* bW    = (const float*)d_in[6];  // [4, 512]
    float* out = (float*)d_out;                  // [2, B, 512]

    int B = in_sizes[0] / 256;

    cudaFuncSetAttribute(lstm_mma_kernel,
                         cudaFuncAttributeMaxDynamicSharedMemorySize, SM_TOTAL);

    lstm_wprep<<<(2048 * 768 + 255) / 256, 256>>>(U, W);
    lstm_zprep<<<(B * 192 + 255) / 256, 256>>>(x, h_old);

    dim3 grid(2048 / BN, B / BM);   // (16, 256) — n fastest for L2 A-stripe reuse
    lstm_mma_kernel<<<grid, NTHR, SM_TOTAL>>>(c_old, bU, bW, out, B);
}

// round 5
// speedup vs baseline: 2.1790x; 1.3387x over previous
#include <cuda_runtime.h>
#include <cuda_bf16.h>
#include <cstdint>

// ============================================================================
// Fused LSTM cell via mma.sync bf16 split-GEMM (plain sm_103 PTX).
//   g[b, n] = sum_k Z[b,k] * Vt[n,k],  Z = [x | h_old] (K=768),
//   n = (h<<2)|g interleaved gate-columns (2048 total).
//   Split: a = a_hi + a_lo (bf16); D += Ah*Bh + Ah*Bl + Al*Bh  (fp32 accum).
// R5: BM=128/BN=64, 48KB stages, 2 CTAs/SM (16 warps/SM) for latency hiding;
//     Bh fragments reused across products 1 and 3.
// ============================================================================

#define BM 128
#define BN 64
#define BK 64
#define NIT 12              // 768 / 64
#define NTHR 256

#define SA_H 0
#define SA_L 16384
#define SB_H 32768
#define SB_L 40960
#define STAGE_BYTES 49152   // 48 KB
#define SM_TOTAL (2 * STAGE_BYTES)   // 96 KB -> 2 CTAs/SM
#define EPI_LD 72                    // padded f32 row stride for epilogue

__device__ __align__(16) __nv_bfloat16 g_Vhi[2048 * 768];
__device__ __align__(16) __nv_bfloat16 g_Vlo[2048 * 768];
__device__ __align__(16) __nv_bfloat16 g_Zhi[65536 * 768];
__device__ __align__(16) __nv_bfloat16 g_Zlo[65536 * 768];

// ---------------------------------------------------------------------------
__device__ __forceinline__ uint32_t smem_u32(const void* p) {
    uint32_t a;
    asm("{ .reg .u64 t; cvta.to.shared.u64 t, %1; cvt.u32.u64 %0, t; }" : "=r"(a) : "l"(p));
    return a;
}
__device__ __forceinline__ uint32_t swz(uint32_t off) { return off ^ ((off >> 3) & 0x70); }

__device__ __forceinline__ void cp16(uint32_t dst, const void* src) {
    asm volatile("cp.async.cg.shared.global [%0], [%1], 16;" :: "r"(dst), "l"(src) : "memory");
}
#define CP_COMMIT() asm volatile("cp.async.commit_group;" ::: "memory")
template <int N> __device__ __forceinline__ void cp_wait() {
    asm volatile("cp.async.wait_group %0;" :: "n"(N) : "memory");
}

__device__ __forceinline__ void ldm4(uint32_t r[4], uint32_t a) {
    asm volatile("ldmatrix.sync.aligned.m8n8.x4.shared.b16 {%0,%1,%2,%3}, [%4];"
        : "=r"(r[0]), "=r"(r[1]), "=r"(r[2]), "=r"(r[3]) : "r"(a));
}
__device__ __forceinline__ void mma16816(float d[4], const uint32_t a[4],
                                         uint32_t b0, uint32_t b1) {
    asm volatile(
        "mma.sync.aligned.m16n8k16.row.col.f32.bf16.bf16.f32 "
        "{%0,%1,%2,%3}, {%4,%5,%6,%7}, {%8,%9}, {%0,%1,%2,%3};"
        : "+f"(d[0]), "+f"(d[1]), "+f"(d[2]), "+f"(d[3])
        : "r"(a[0]), "r"(a[1]), "r"(a[2]), "r"(a[3]), "r"(b0), "r"(b1));
}

__device__ __forceinline__ float sigmoidf_(float x) {
    return 1.0f / (1.0f + __expf(-x));
}
__device__ __forceinline__ float tanhf_(float x) {
    return 2.0f / (1.0f + __expf(-2.0f * x)) - 1.0f;
}

// ---------------------------------------------------------------------------
// Prep 1: transpose + hi/lo split weights. Vt[n][k], n = (h<<2)|g.
// ---------------------------------------------------------------------------
__global__ void lstm_wprep(const float* __restrict__ U, const float* __restrict__ W) {
    int idx = blockIdx.x * blockDim.x + threadIdx.x;
    if (idx >= 2048 * 768) return;
    int n = idx / 768, kk = idx - n * 768;
    int g = n & 3, h = n >> 2;
    float v = (kk < 256) ? U[((size_t)g * 256 + kk) * 512 + h]
                         : W[((size_t)g * 512 + (kk - 256)) * 512 + h];
    __nv_bfloat16 hi = __float2bfloat16(v);
    g_Vhi[idx] = hi;
    g_Vlo[idx] = __float2bfloat16(v - __bfloat162float(hi));
}

// ---------------------------------------------------------------------------
// Prep 2: hi/lo split Z = [x | h_old] -> g_Zhi/g_Zlo [B][768].
// ---------------------------------------------------------------------------
__global__ void lstm_zprep(const float* __restrict__ x, const float* __restrict__ h_old) {
    int idx = blockIdx.x * blockDim.x + threadIdx.x;   // one float4 each
    int m = idx / 192;
    int k = (idx - m * 192) * 4;
    float4 v = (k < 256)
        ? *reinterpret_cast<const float4*>(x + (size_t)m * 256 + k)
        : *reinterpret_cast<const float4*>(h_old + (size_t)m * 512 + (k - 256));
    __nv_bfloat162 h01 = __float22bfloat162_rn(make_float2(v.x, v.y));
    __nv_bfloat162 h23 = __float22bfloat162_rn(make_float2(v.z, v.w));
    float2 f01 = __bfloat1622float2(h01);
    float2 f23 = __bfloat1622float2(h23);
    __nv_bfloat162 l01 = __float22bfloat162_rn(make_float2(v.x - f01.x, v.y - f01.y));
    __nv_bfloat162 l23 = __float22bfloat162_rn(make_float2(v.z - f23.x, v.w - f23.y));
    uint2 hp, lp;
    hp.x = *reinterpret_cast<uint32_t*>(&h01); hp.y = *reinterpret_cast<uint32_t*>(&h23);
    lp.x = *reinterpret_cast<uint32_t*>(&l01); lp.y = *reinterpret_cast<uint32_t*>(&l23);
    *reinterpret_cast<uint2*>(g_Zhi + (size_t)m * 768 + k) = hp;
    *reinterpret_cast<uint2*>(g_Zlo + (size_t)m * 768 + k) = lp;
}

// ---------------------------------------------------------------------------
// Stage fill: 12 cp.async x 16B per thread.
//   A: 128 rows x 128B (hi @SA_H, lo @SA_L);  B: 64 rows x 128B (hi/lo).
// ---------------------------------------------------------------------------
__device__ __forceinline__ void fill_stage(uint32_t sst, int it, int tid, int m0, int n0g) {
    const int kt2 = it * 128;   // byte offset within 1536-byte k-row
    // ---- A: thread t -> row t>>1, k-half (t&1)*64, 4 chunks, hi+lo ----
    {
        const int row = tid >> 1;
        const int kh  = (tid & 1) * 64;
        const char* sh = (const char*)g_Zhi + (size_t)(m0 + row) * 1536 + kt2 + kh;
        const char* sl = (const char*)g_Zlo + (size_t)(m0 + row) * 1536 + kt2 + kh;
        #pragma unroll
        for (int c = 0; c < 4; c++) {
            uint32_t so = swz((uint32_t)(row * 128 + kh + c * 16));
            cp16(sst + SA_H + so, sh + c * 16);
            cp16(sst + SA_L + so, sl + c * 16);
        }
    }
    // ---- B: threads 0-127 -> hi, 128-255 -> lo; row (t&127)>>1, half (t&1) ----
    {
        const int row = (tid & 127) >> 1;
        const int kh  = (tid & 1) * 64;
        const __nv_bfloat16* base = (tid & 128) ? g_Vlo : g_Vhi;
        const uint32_t db = sst + ((tid & 128) ? SB_L : SB_H);
        const char* src = (const char*)base + (size_t)(n0g + row) * 1536 + kt2 + kh;
        #pragma unroll
        for (int c = 0; c < 4; c++)
            cp16(db + swz((uint32_t)(row * 128 + kh + c * 16)), src + c * 16);
    }
}

// ---------------------------------------------------------------------------
// Main GEMM + epilogue. 8 warps, warp tile 32x32 (4m x 2n warp grid).
// ---------------------------------------------------------------------------
__global__ __launch_bounds__(NTHR, 2)
void lstm_mma_kernel(const float* __restrict__ c_old,
                     const float* __restrict__ bU,
                     const float* __restrict__ bW,
                     float* __restrict__ out,
                     int B)
{
    extern __shared__ char sm[];
    const uint32_t sb = smem_u32(sm);
    const int tid  = threadIdx.x;
    const int wid  = tid >> 5;
    const int lane = tid & 31;

    const int m0  = blockIdx.y * BM;
    const int n0g = blockIdx.x * BN;
    const int h0  = blockIdx.x * 16;

    const int wm = (wid >> 1) * 32;   // warp m offset (4 tiles -> 128)
    const int wn = (wid & 1) * 32;    // warp n offset (2 tiles -> 64)

    const int a_row = lane & 15;
    const int a_kh  = (lane >> 4) * 16;
    const int b_row = (lane & 7) + ((lane & 16) >> 1);
    const int b_kh  = ((lane >> 3) & 1) * 16;

    float acc[2][4][4];
    #pragma unroll
    for (int mt = 0; mt < 2; mt++)
        #pragma unroll
        for (int nt = 0; nt < 4; nt++)
            #pragma unroll
            for (int r = 0; r < 4; r++) acc[mt][nt][r] = 0.0f;

    // ---- pipeline prologue ----
    fill_stage(sb, 0, tid, m0, n0g);               CP_COMMIT();
    fill_stage(sb + STAGE_BYTES, 1, tid, m0, n0g); CP_COMMIT();
    cp_wait<1>();
    __syncthreads();

    for (int it = 0; it < NIT; it++) {
        const uint32_t st = sb + (uint32_t)(it & 1) * STAGE_BYTES;

        #pragma unroll
        for (int ks = 0; ks < 4; ks++) {
            const uint32_t kb = ks * 32;
            uint32_t ah[2][4], al[2][4], bh[2][4], bl[2][4];

            #pragma unroll
            for (int mt = 0; mt < 2; mt++)
                ldm4(ah[mt], st + SA_H + swz((uint32_t)((wm + mt * 16 + a_row) * 128 + kb + a_kh)));
            #pragma unroll
            for (int p = 0; p < 2; p++)
                ldm4(bh[p], st + SB_H + swz((uint32_t)((wn + p * 16 + b_row) * 128 + kb + b_kh)));

            // product 1: Ah * Bh
            #pragma unroll
            for (int mt = 0; mt < 2; mt++)
                #pragma unroll
                for (int nt = 0; nt < 4; nt++)
                    mma16816(acc[mt][nt], ah[mt], bh[nt >> 1][(nt & 1) * 2], bh[nt >> 1][(nt & 1) * 2 + 1]);

            #pragma unroll
            for (int p = 0; p < 2; p++)
                ldm4(bl[p], st + SB_L + swz((uint32_t)((wn + p * 16 + b_row) * 128 + kb + b_kh)));

            // product 2: Ah * Bl
            #pragma unroll
            for (int mt = 0; mt < 2; mt++)
                #pragma unroll
                for (int nt = 0; nt < 4; nt++)
                    mma16816(acc[mt][nt], ah[mt], bl[nt >> 1][(nt & 1) * 2], bl[nt >> 1][(nt & 1) * 2 + 1]);

            #pragma unroll
            for (int mt = 0; mt < 2; mt++)
                ldm4(al[mt], st + SA_L + swz((uint32_t)((wm + mt * 16 + a_row) * 128 + kb + a_kh)));

            // product 3: Al * Bh (Bh fragments reused)
            #pragma unroll
            for (int mt = 0; mt < 2; mt++)
                #pragma unroll
                for (int nt = 0; nt < 4; nt++)
                    mma16816(acc[mt][nt], al[mt], bh[nt >> 1][(nt & 1) * 2], bh[nt >> 1][(nt & 1) * 2 + 1]);
        }

        __syncthreads();    // all warps done reading this stage
        if (it + 2 < NIT) {
            fill_stage(sb + (uint32_t)(it & 1) * STAGE_BYTES, it + 2, tid, m0, n0g);
            CP_COMMIT();
            cp_wait<1>();
        } else {
            cp_wait<0>();
        }
        __syncthreads();
    }

    // ---- epilogue: accums -> SMEM (row stride 72 f32) ----
    float* epi = reinterpret_cast<float*>(sm);
    #pragma unroll
    for (int mt = 0; mt < 2; mt++) {
        #pragma unroll
        for (int nt = 0; nt < 4; nt++) {
            const int m = wm + mt * 16 + (lane >> 2);
            const int n = wn + nt * 8 + (lane & 3) * 2;
            *reinterpret_cast<float2*>(&epi[m * EPI_LD + n]) =
                make_float2(acc[mt][nt][0], acc[mt][nt][1]);
            *reinterpret_cast<float2*>(&epi[(m + 8) * EPI_LD + n]) =
                make_float2(acc[mt][nt][2], acc[mt][nt][3]);
        }
    }
    __syncthreads();

    // ---- gates + state update ----
    {
        const int h_loc = tid & 15;       // 16 h per CTA
        const int mrow0 = tid >> 4;       // 16 row groups
        const size_t BH = (size_t)B * 512;
        const float bi = bU[0 * 512 + h0 + h_loc] + bW[0 * 512 + h0 + h_loc];
        const float bf = bU[1 * 512 + h0 + h_loc] + bW[1 * 512 + h0 + h_loc];
        const float bo = bU[2 * 512 + h0 + h_loc] + bW[2 * 512 + h0 + h_loc];
        const float bc = bU[3 * 512 + h0 + h_loc] + bW[3 * 512 + h0 + h_loc];

        #pragma unroll
        for (int j = 0; j < 8; j++) {
            const int m = mrow0 + 16 * j;
            float4 gv = *reinterpret_cast<const float4*>(&epi[m * EPI_LD + h_loc * 4]);
            const float i_t = sigmoidf_(gv.x + bi);
            const float f_t = sigmoidf_(gv.y + bf);
            const float o_t = sigmoidf_(gv.z + bo);
            const float c_t = tanhf_(gv.w + bc);
            const size_t off = (size_t)(m0 + m) * 512 + h0 + h_loc;
            const float cn = i_t * c_t + f_t * c_old[off];
            out[off]      = o_t * tanhf_(cn);   // h_new
            out[BH + off] = cn;                 // c_new
        }
    }
}

// ---------------------------------------------------------------------------
extern "C" void kernel_launch(void* const* d_in, const int* in_sizes, int n_in,
                              void* d_out, int out_size)
{
    const float* x     = (const float*)d_in[0];  // [B, 256]
    const float* h_old = (const float*)d_in[1];  // [B, 512]
    const float* c_old = (const float*)d_in[2];  // [B, 512]
    const float* U     = (const float*)d_in[3];  // [4, 256, 512]
    const float* bU    = (const float*)d_in[4];  // [4, 512]
    const float* W     = (const float*)d_in[5];  // [4, 512, 512]
    const float* bW    = (const float*)d_in[6];  // [4, 512]
    float* out = (float*)d_out;                  // [2, B, 512]

    int B = in_sizes[0] / 256;

    cudaFuncSetAttribute(lstm_mma_kernel,
                         cudaFuncAttributeMaxDynamicSharedMemorySize, SM_TOTAL);

    lstm_wprep<<<(2048 * 768 + 255) / 256, 256>>>(U, W);
    lstm_zprep<<<(B * 192 + 255) / 256, 256>>>(x, h_old);

    dim3 grid(2048 / BN, B / BM);   // (32, 512) — n fastest for L2 A-stripe reuse
    lstm_mma_kernel<<<grid, NTHR, SM_TOTAL>>>(c_old, bU, bW, out, B);
}

// round 6
// speedup vs baseline: 2.9303x; 1.3448x over previous
#include <cuda_runtime.h>
#include <cuda_fp16.h>
#include <cstdint>

// ============================================================================
// Fused LSTM cell via mma.sync fp16 2-product split-GEMM (plain sm_103 PTX).
//   g[b, n] = sum_k Z[b,k] * Vt[n,k],  Z = [x | h_old] (K=768),
//   n = (h<<2)|g interleaved gate-columns (2048 total).
//   Split: z = z_hi + z_lo (fp16), V single-rounded fp16;
//          D += Zh*V + Zl*V  (fp32 accum).  Residual error ~ V rounding ~2^-12.
// R6: 2 products instead of 3 (HMMA count -33% vs bf16 split); B frags reused.
// ============================================================================

#define BM 128
#define BN 64
#define BK 64
#define NIT 12              // 768 / 64
#define NTHR 256

#define SA_H 0
#define SA_L 16384
#define SB   32768
#define STAGE_BYTES 40960   // 40 KB: Ah 16K + Al 16K + B 8K
#define SM_TOTAL (2 * STAGE_BYTES)   // 80 KB -> 2 CTAs/SM
#define EPI_LD 72                    // padded f32 row stride for epilogue

__device__ __align__(16) __half g_V  [2048 * 768];
__device__ __align__(16) __half g_Zhi[65536 * 768];
__device__ __align__(16) __half g_Zlo[65536 * 768];

// ---------------------------------------------------------------------------
__device__ __forceinline__ uint32_t smem_u32(const void* p) {
    uint32_t a;
    asm("{ .reg .u64 t; cvta.to.shared.u64 t, %1; cvt.u32.u64 %0, t; }" : "=r"(a) : "l"(p));
    return a;
}
__device__ __forceinline__ uint32_t swz(uint32_t off) { return off ^ ((off >> 3) & 0x70); }

__device__ __forceinline__ void cp16(uint32_t dst, const void* src) {
    asm volatile("cp.async.cg.shared.global [%0], [%1], 16;" :: "r"(dst), "l"(src) : "memory");
}
#define CP_COMMIT() asm volatile("cp.async.commit_group;" ::: "memory")
template <int N> __device__ __forceinline__ void cp_wait() {
    asm volatile("cp.async.wait_group %0;" :: "n"(N) : "memory");
}

__device__ __forceinline__ void ldm4(uint32_t r[4], uint32_t a) {
    asm volatile("ldmatrix.sync.aligned.m8n8.x4.shared.b16 {%0,%1,%2,%3}, [%4];"
        : "=r"(r[0]), "=r"(r[1]), "=r"(r[2]), "=r"(r[3]) : "r"(a));
}
__device__ __forceinline__ void mma16816(float d[4], const uint32_t a[4],
                                         uint32_t b0, uint32_t b1) {
    asm volatile(
        "mma.sync.aligned.m16n8k16.row.col.f32.f16.f16.f32 "
        "{%0,%1,%2,%3}, {%4,%5,%6,%7}, {%8,%9}, {%0,%1,%2,%3};"
        : "+f"(d[0]), "+f"(d[1]), "+f"(d[2]), "+f"(d[3])
        : "r"(a[0]), "r"(a[1]), "r"(a[2]), "r"(a[3]), "r"(b0), "r"(b1));
}

__device__ __forceinline__ float sigmoidf_(float x) {
    return 1.0f / (1.0f + __expf(-x));
}
__device__ __forceinline__ float tanhf_(float x) {
    return 2.0f / (1.0f + __expf(-2.0f * x)) - 1.0f;
}

// ---------------------------------------------------------------------------
// Prep 1: transpose + fp16 round weights. Vt[n][k], n = (h<<2)|g.
// ---------------------------------------------------------------------------
__global__ void lstm_wprep(const float* __restrict__ U, const float* __restrict__ W) {
    int idx = blockIdx.x * blockDim.x + threadIdx.x;
    if (idx >= 2048 * 768) return;
    int n = idx / 768, kk = idx - n * 768;
    int g = n & 3, h = n >> 2;
    float v = (kk < 256) ? U[((size_t)g * 256 + kk) * 512 + h]
                         : W[((size_t)g * 512 + (kk - 256)) * 512 + h];
    g_V[idx] = __float2half_rn(v);
}

// ---------------------------------------------------------------------------
// Prep 2: fp16 hi/lo split of Z = [x | h_old] -> g_Zhi/g_Zlo [B][768].
// ---------------------------------------------------------------------------
__global__ void lstm_zprep(const float* __restrict__ x, const float* __restrict__ h_old) {
    int idx = blockIdx.x * blockDim.x + threadIdx.x;   // one float4 each
    int m = idx / 192;
    int k = (idx - m * 192) * 4;
    float4 v = (k < 256)
        ? *reinterpret_cast<const float4*>(x + (size_t)m * 256 + k)
        : *reinterpret_cast<const float4*>(h_old + (size_t)m * 512 + (k - 256));
    __half2 h01 = __float22half2_rn(make_float2(v.x, v.y));
    __half2 h23 = __float22half2_rn(make_float2(v.z, v.w));
    float2 f01 = __half22float2(h01);
    float2 f23 = __half22float2(h23);
    __half2 l01 = __float22half2_rn(make_float2(v.x - f01.x, v.y - f01.y));
    __half2 l23 = __float22half2_rn(make_float2(v.z - f23.x, v.w - f23.y));
    uint2 hp, lp;
    hp.x = *reinterpret_cast<uint32_t*>(&h01); hp.y = *reinterpret_cast<uint32_t*>(&h23);
    lp.x = *reinterpret_cast<uint32_t*>(&l01); lp.y = *reinterpret_cast<uint32_t*>(&l23);
    *reinterpret_cast<uint2*>(g_Zhi + (size_t)m * 768 + k) = hp;
    *reinterpret_cast<uint2*>(g_Zlo + (size_t)m * 768 + k) = lp;
}

// ---------------------------------------------------------------------------
// Stage fill: 10 cp.async x 16B per thread.
//   A: 128 rows x 128B (hi @SA_H, lo @SA_L);  B: 64 rows x 128B (single).
// ---------------------------------------------------------------------------
__device__ __forceinline__ void fill_stage(uint32_t sst, int it, int tid, int m0, int n0g) {
    const int kt2 = it * 128;   // byte offset within 1536-byte k-row
    // ---- A: thread t -> row t>>1, k-half (t&1)*64, 4 chunks, hi+lo ----
    {
        const int row = tid >> 1;
        const int kh  = (tid & 1) * 64;
        const char* sh = (const char*)g_Zhi + (size_t)(m0 + row) * 1536 + kt2 + kh;
        const char* sl = (const char*)g_Zlo + (size_t)(m0 + row) * 1536 + kt2 + kh;
        #pragma unroll
        for (int c = 0; c < 4; c++) {
            uint32_t so = swz((uint32_t)(row * 128 + kh + c * 16));
            cp16(sst + SA_H + so, sh + c * 16);
            cp16(sst + SA_L + so, sl + c * 16);
        }
    }
    // ---- B: thread t -> row t>>2, chunk pair (t&3)*2 ----
    {
        const int row = tid >> 2;
        const int c0  = (tid & 3) * 2;
        const char* src = (const char*)g_V + (size_t)(n0g + row) * 1536 + kt2 + c0 * 16;
        #pragma unroll
        for (int c = 0; c < 2; c++)
            cp16(sst + SB + swz((uint32_t)(row * 128 + (c0 + c) * 16)), src + c * 16);
    }
}

// ---------------------------------------------------------------------------
// Main GEMM + epilogue. 8 warps, warp tile 32x32 (4m x 2n warp grid).
// ---------------------------------------------------------------------------
__global__ __launch_bounds__(NTHR, 2)
void lstm_mma_kernel(const float* __restrict__ c_old,
                     const float* __restrict__ bU,
                     const float* __restrict__ bW,
                     float* __restrict__ out,
                     int B)
{
    extern __shared__ char sm[];
    const uint32_t sb = smem_u32(sm);
    const int tid  = threadIdx.x;
    const int wid  = tid >> 5;
    const int lane = tid & 31;

    const int m0  = blockIdx.y * BM;
    const int n0g = blockIdx.x * BN;
    const int h0  = blockIdx.x * 16;

    const int wm = (wid >> 1) * 32;   // warp m offset (4 tiles -> 128)
    const int wn = (wid & 1) * 32;    // warp n offset (2 tiles -> 64)

    const int a_row = lane & 15;
    const int a_kh  = (lane >> 4) * 16;
    const int b_row = (lane & 7) + ((lane & 16) >> 1);
    const int b_kh  = ((lane >> 3) & 1) * 16;

    float acc[2][4][4];
    #pragma unroll
    for (int mt = 0; mt < 2; mt++)
        #pragma unroll
        for (int nt = 0; nt < 4; nt++)
            #pragma unroll
            for (int r = 0; r < 4; r++) acc[mt][nt][r] = 0.0f;

    // ---- pipeline prologue ----
    fill_stage(sb, 0, tid, m0, n0g);               CP_COMMIT();
    fill_stage(sb + STAGE_BYTES, 1, tid, m0, n0g); CP_COMMIT();
    cp_wait<1>();
    __syncthreads();

    for (int it = 0; it < NIT; it++) {
        const uint32_t st = sb + (uint32_t)(it & 1) * STAGE_BYTES;

        #pragma unroll
        for (int ks = 0; ks < 4; ks++) {
            const uint32_t kb = ks * 32;
            uint32_t ah[2][4], al[2][4], bb[2][4];

            #pragma unroll
            for (int mt = 0; mt < 2; mt++)
                ldm4(ah[mt], st + SA_H + swz((uint32_t)((wm + mt * 16 + a_row) * 128 + kb + a_kh)));
            #pragma unroll
            for (int p = 0; p < 2; p++)
                ldm4(bb[p], st + SB + swz((uint32_t)((wn + p * 16 + b_row) * 128 + kb + b_kh)));

            // product 1: Zh * V
            #pragma unroll
            for (int mt = 0; mt < 2; mt++)
                #pragma unroll
                for (int nt = 0; nt < 4; nt++)
                    mma16816(acc[mt][nt], ah[mt], bb[nt >> 1][(nt & 1) * 2], bb[nt >> 1][(nt & 1) * 2 + 1]);

            #pragma unroll
            for (int mt = 0; mt < 2; mt++)
                ldm4(al[mt], st + SA_L + swz((uint32_t)((wm + mt * 16 + a_row) * 128 + kb + a_kh)));

            // product 2: Zl * V (B fragments reused)
            #pragma unroll
            for (int mt = 0; mt < 2; mt++)
                #pragma unroll
                for (int nt = 0; nt < 4; nt++)
                    mma16816(acc[mt][nt], al[mt], bb[nt >> 1][(nt & 1) * 2], bb[nt >> 1][(nt & 1) * 2 + 1]);
        }

        __syncthreads();    // all warps done reading this stage
        if (it + 2 < NIT) {
            fill_stage(sb + (uint32_t)(it & 1) * STAGE_BYTES, it + 2, tid, m0, n0g);
            CP_COMMIT();
            cp_wait<1>();
        } else {
            cp_wait<0>();
        }
        __syncthreads();
    }

    // ---- epilogue: accums -> SMEM (row stride 72 f32) ----
    float* epi = reinterpret_cast<float*>(sm);
    #pragma unroll
    for (int mt = 0; mt < 2; mt++) {
        #pragma unroll
        for (int nt = 0; nt < 4; nt++) {
            const int m = wm + mt * 16 + (lane >> 2);
            const int n = wn + nt * 8 + (lane & 3) * 2;
            *reinterpret_cast<float2*>(&epi[m * EPI_LD + n]) =
                make_float2(acc[mt][nt][0], acc[mt][nt][1]);
            *reinterpret_cast<float2*>(&epi[(m + 8) * EPI_LD + n]) =
                make_float2(acc[mt][nt][2], acc[mt][nt][3]);
        }
    }
    __syncthreads();

    // ---- gates + state update ----
    {
        const int h_loc = tid & 15;       // 16 h per CTA
        const int mrow0 = tid >> 4;       // 16 row groups
        const size_t BH = (size_t)B * 512;
        const float bi = bU[0 * 512 + h0 + h_loc] + bW[0 * 512 + h0 + h_loc];
        const float bf = bU[1 * 512 + h0 + h_loc] + bW[1 * 512 + h0 + h_loc];
        const float bo = bU[2 * 512 + h0 + h_loc] + bW[2 * 512 + h0 + h_loc];
        const float bc = bU[3 * 512 + h0 + h_loc] + bW[3 * 512 + h0 + h_loc];

        #pragma unroll
        for (int j = 0; j < 8; j++) {
            const int m = mrow0 + 16 * j;
            float4 gv = *reinterpret_cast<const float4*>(&epi[m * EPI_LD + h_loc * 4]);
            const float i_t = sigmoidf_(gv.x + bi);
            const float f_t = sigmoidf_(gv.y + bf);
            const float o_t = sigmoidf_(gv.z + bo);
            const float c_t = tanhf_(gv.w + bc);
            const size_t off = (size_t)(m0 + m) * 512 + h0 + h_loc;
            const float cn = i_t * c_t + f_t * c_old[off];
            out[off]      = o_t * tanhf_(cn);   // h_new
            out[BH + off] = cn;                 // c_new
        }
    }
}

// ---------------------------------------------------------------------------
extern "C" void kernel_launch(void* const* d_in, const int* in_sizes, int n_in,
                              void* d_out, int out_size)
{
    const float* x     = (const float*)d_in[0];  // [B, 256]
    const float* h_old = (const float*)d_in[1];  // [B, 512]
    const float* c_old = (const float*)d_in[2];  // [B, 512]
    const float* U     = (const float*)d_in[3];  // [4, 256, 512]
    const float* bU    = (const float*)d_in[4];  // [4, 512]
    const float* W     = (const float*)d_in[5];  // [4, 512, 512]
    const float* bW    = (const float*)d_in[6];  // [4, 512]
    float* out = (float*)d_out;                  // [2, B, 512]

    int B = in_sizes[0] / 256;

    cudaFuncSetAttribute(lstm_mma_kernel,
                         cudaFuncAttributeMaxDynamicSharedMemorySize, SM_TOTAL);

    lstm_wprep<<<(2048 * 768 + 255) / 256, 256>>>(U, W);
    lstm_zprep<<<(B * 192 + 255) / 256, 256>>>(x, h_old);

    dim3 grid(2048 / BN, B / BM);   // (32, 512) — n fastest for L2 A-stripe reuse
    lstm_mma_kernel<<<grid, NTHR, SM_TOTAL>>>(c_old, bU, bW, out, B);
}

// round 7
// speedup vs baseline: 4.4536x; 1.5198x over previous
#include <cuda_runtime.h>
#include <cuda_fp16.h>
#include <cstdint>

// ============================================================================
// Fused LSTM cell via plain fp16 mma.sync GEMM (plain sm_103 PTX).
//   g[b, n] = sum_k Z[b,k] * Vt[n,k],  Z = [x | h_old] (K=768),
//   n = (h<<2)|g interleaved gate-columns (2048 total).
//   Single product: both Z and V rounded to fp16, fp32 accumulate.
//   Expected rel err ~3-4e-4 (vs 1e-3 gate).
// R7: HMMA count halved vs R6 (5.0e7 instrs) — mma.sync is rt=16/SMSP bound.
// ============================================================================

#define BM 128
#define BN 64
#define BK 64
#define NIT 12              // 768 / 64
#define NTHR 256

#define SA   0
#define SB   16384
#define STAGE_BYTES 24576   // 24 KB: A 16K + B 8K
#define SM_TOTAL (2 * STAGE_BYTES)   // 48 KB -> 2 CTAs/SM easily
#define EPI_LD 72                    // padded f32 row stride for epilogue

__device__ __align__(16) __half g_V[2048 * 768];
__device__ __align__(16) __half g_Z[65536 * 768];

// ---------------------------------------------------------------------------
__device__ __forceinline__ uint32_t smem_u32(const void* p) {
    uint32_t a;
    asm("{ .reg .u64 t; cvta.to.shared.u64 t, %1; cvt.u32.u64 %0, t; }" : "=r"(a) : "l"(p));
    return a;
}
__device__ __forceinline__ uint32_t swz(uint32_t off) { return off ^ ((off >> 3) & 0x70); }

__device__ __forceinline__ void cp16(uint32_t dst, const void* src) {
    asm volatile("cp.async.cg.shared.global [%0], [%1], 16;" :: "r"(dst), "l"(src) : "memory");
}
#define CP_COMMIT() asm volatile("cp.async.commit_group;" ::: "memory")
template <int N> __device__ __forceinline__ void cp_wait() {
    asm volatile("cp.async.wait_group %0;" :: "n"(N) : "memory");
}

__device__ __forceinline__ void ldm4(uint32_t r[4], uint32_t a) {
    asm volatile("ldmatrix.sync.aligned.m8n8.x4.shared.b16 {%0,%1,%2,%3}, [%4];"
        : "=r"(r[0]), "=r"(r[1]), "=r"(r[2]), "=r"(r[3]) : "r"(a));
}
__device__ __forceinline__ void mma16816(float d[4], const uint32_t a[4],
                                         uint32_t b0, uint32_t b1) {
    asm volatile(
        "mma.sync.aligned.m16n8k16.row.col.f32.f16.f16.f32 "
        "{%0,%1,%2,%3}, {%4,%5,%6,%7}, {%8,%9}, {%0,%1,%2,%3};"
        : "+f"(d[0]), "+f"(d[1]), "+f"(d[2]), "+f"(d[3])
        : "r"(a[0]), "r"(a[1]), "r"(a[2]), "r"(a[3]), "r"(b0), "r"(b1));
}

__device__ __forceinline__ float sigmoidf_(float x) {
    return 1.0f / (1.0f + __expf(-x));
}
__device__ __forceinline__ float tanhf_(float x) {
    return 2.0f / (1.0f + __expf(-2.0f * x)) - 1.0f;
}

// ---------------------------------------------------------------------------
// Prep 1: transpose + fp16 round weights. Vt[n][k], n = (h<<2)|g.
// ---------------------------------------------------------------------------
__global__ void lstm_wprep(const float* __restrict__ U, const float* __restrict__ W) {
    int idx = blockIdx.x * blockDim.x + threadIdx.x;
    if (idx >= 2048 * 768) return;
    int n = idx / 768, kk = idx - n * 768;
    int g = n & 3, h = n >> 2;
    float v = (kk < 256) ? U[((size_t)g * 256 + kk) * 512 + h]
                         : W[((size_t)g * 512 + (kk - 256)) * 512 + h];
    g_V[idx] = __float2half_rn(v);
}

// ---------------------------------------------------------------------------
// Prep 2: fp16 round of Z = [x | h_old] -> g_Z [B][768].
// ---------------------------------------------------------------------------
__global__ void lstm_zprep(const float* __restrict__ x, const float* __restrict__ h_old) {
    int idx = blockIdx.x * blockDim.x + threadIdx.x;   // one float4 each
    int m = idx / 192;
    int k = (idx - m * 192) * 4;
    float4 v = (k < 256)
        ? *reinterpret_cast<const float4*>(x + (size_t)m * 256 + k)
        : *reinterpret_cast<const float4*>(h_old + (size_t)m * 512 + (k - 256));
    __half2 h01 = __float22half2_rn(make_float2(v.x, v.y));
    __half2 h23 = __float22half2_rn(make_float2(v.z, v.w));
    uint2 hp;
    hp.x = *reinterpret_cast<uint32_t*>(&h01);
    hp.y = *reinterpret_cast<uint32_t*>(&h23);
    *reinterpret_cast<uint2*>(g_Z + (size_t)m * 768 + k) = hp;
}

// ---------------------------------------------------------------------------
// Stage fill: 6 cp.async x 16B per thread.
//   A: 128 rows x 128B;  B: 64 rows x 128B.
// ---------------------------------------------------------------------------
__device__ __forceinline__ void fill_stage(uint32_t sst, int it, int tid, int m0, int n0g) {
    const int kt2 = it * 128;   // byte offset within 1536-byte k-row
    // ---- A: thread t -> row t>>1, k-half (t&1)*64, 4 chunks ----
    {
        const int row = tid >> 1;
        const int kh  = (tid & 1) * 64;
        const char* src = (const char*)g_Z + (size_t)(m0 + row) * 1536 + kt2 + kh;
        #pragma unroll
        for (int c = 0; c < 4; c++)
            cp16(sst + SA + swz((uint32_t)(row * 128 + kh + c * 16)), src + c * 16);
    }
    // ---- B: thread t -> row t>>2, chunk pair (t&3)*2 ----
    {
        const int row = tid >> 2;
        const int c0  = (tid & 3) * 2;
        const char* src = (const char*)g_V + (size_t)(n0g + row) * 1536 + kt2 + c0 * 16;
        #pragma unroll
        for (int c = 0; c < 2; c++)
            cp16(sst + SB + swz((uint32_t)(row * 128 + (c0 + c) * 16)), src + c * 16);
    }
}

// ---------------------------------------------------------------------------
// Main GEMM + epilogue. 8 warps, warp tile 32x32 (4m x 2n warp grid).
// ---------------------------------------------------------------------------
__global__ __launch_bounds__(NTHR, 2)
void lstm_mma_kernel(const float* __restrict__ c_old,
                     const float* __restrict__ bU,
                     const float* __restrict__ bW,
                     float* __restrict__ out,
                     int B)
{
    extern __shared__ char sm[];
    const uint32_t sb = smem_u32(sm);
    const int tid  = threadIdx.x;
    const int wid  = tid >> 5;
    const int lane = tid & 31;

    const int m0  = blockIdx.y * BM;
    const int n0g = blockIdx.x * BN;
    const int h0  = blockIdx.x * 16;

    const int wm = (wid >> 1) * 32;   // warp m offset (4 tiles -> 128)
    const int wn = (wid & 1) * 32;    // warp n offset (2 tiles -> 64)

    const int a_row = lane & 15;
    const int a_kh  = (lane >> 4) * 16;
    const int b_row = (lane & 7) + ((lane & 16) >> 1);
    const int b_kh  = ((lane >> 3) & 1) * 16;

    float acc[2][4][4];
    #pragma unroll
    for (int mt = 0; mt < 2; mt++)
        #pragma unroll
        for (int nt = 0; nt < 4; nt++)
            #pragma unroll
            for (int r = 0; r < 4; r++) acc[mt][nt][r] = 0.0f;

    // ---- pipeline prologue ----
    fill_stage(sb, 0, tid, m0, n0g);               CP_COMMIT();
    fill_stage(sb + STAGE_BYTES, 1, tid, m0, n0g); CP_COMMIT();
    cp_wait<1>();
    __syncthreads();

    for (int it = 0; it < NIT; it++) {
        const uint32_t st = sb + (uint32_t)(it & 1) * STAGE_BYTES;

        #pragma unroll
        for (int ks = 0; ks < 4; ks++) {
            const uint32_t kb = ks * 32;
            uint32_t aa[2][4], bb[2][4];

            #pragma unroll
            for (int mt = 0; mt < 2; mt++)
                ldm4(aa[mt], st + SA + swz((uint32_t)((wm + mt * 16 + a_row) * 128 + kb + a_kh)));
            #pragma unroll
            for (int p = 0; p < 2; p++)
                ldm4(bb[p], st + SB + swz((uint32_t)((wn + p * 16 + b_row) * 128 + kb + b_kh)));

            #pragma unroll
            for (int mt = 0; mt < 2; mt++)
                #pragma unroll
                for (int nt = 0; nt < 4; nt++)
                    mma16816(acc[mt][nt], aa[mt], bb[nt >> 1][(nt & 1) * 2], bb[nt >> 1][(nt & 1) * 2 + 1]);
        }

        __syncthreads();    // all warps done reading this stage
        if (it + 2 < NIT) {
            fill_stage(sb + (uint32_t)(it & 1) * STAGE_BYTES, it + 2, tid, m0, n0g);
            CP_COMMIT();
            cp_wait<1>();
        } else {
            cp_wait<0>();
        }
        __syncthreads();
    }

    // ---- epilogue: accums -> SMEM (row stride 72 f32) ----
    float* epi = reinterpret_cast<float*>(sm);
    #pragma unroll
    for (int mt = 0; mt < 2; mt++) {
        #pragma unroll
        for (int nt = 0; nt < 4; nt++) {
            const int m = wm + mt * 16 + (lane >> 2);
            const int n = wn + nt * 8 + (lane & 3) * 2;
            *reinterpret_cast<float2*>(&epi[m * EPI_LD + n]) =
                make_float2(acc[mt][nt][0], acc[mt][nt][1]);
            *reinterpret_cast<float2*>(&epi[(m + 8) * EPI_LD + n]) =
                make_float2(acc[mt][nt][2], acc[mt][nt][3]);
        }
    }
    __syncthreads();

    // ---- gates + state update ----
    {
        const int h_loc = tid & 15;       // 16 h per CTA
        const int mrow0 = tid >> 4;       // 16 row groups
        const size_t BH = (size_t)B * 512;
        const float bi = bU[0 * 512 + h0 + h_loc] + bW[0 * 512 + h0 + h_loc];
        const float bf = bU[1 * 512 + h0 + h_loc] + bW[1 * 512 + h0 + h_loc];
        const float bo = bU[2 * 512 + h0 + h_loc] + bW[2 * 512 + h0 + h_loc];
        const float bc = bU[3 * 512 + h0 + h_loc] + bW[3 * 512 + h0 + h_loc];

        #pragma unroll
        for (int j = 0; j < 8; j++) {
            const int m = mrow0 + 16 * j;
            float4 gv = *reinterpret_cast<const float4*>(&epi[m * EPI_LD + h_loc * 4]);
            const float i_t = sigmoidf_(gv.x + bi);
            const float f_t = sigmoidf_(gv.y + bf);
            const float o_t = sigmoidf_(gv.z + bo);
            const float c_t = tanhf_(gv.w + bc);
            const size_t off = (size_t)(m0 + m) * 512 + h0 + h_loc;
            const float cn = i_t * c_t + f_t * c_old[off];
            out[off]      = o_t * tanhf_(cn);   // h_new
            out[BH + off] = cn;                 // c_new
        }
    }
}

// ---------------------------------------------------------------------------
extern "C" void kernel_launch(void* const* d_in, const int* in_sizes, int n_in,
                              void* d_out, int out_size)
{
    const float* x     = (const float*)d_in[0];  // [B, 256]
    const float* h_old = (const float*)d_in[1];  // [B, 512]
    const float* c_old = (const float*)d_in[2];  // [B, 512]
    const float* U     = (const float*)d_in[3];  // [4, 256, 512]
    const float* bU    = (const float*)d_in[4];  // [4, 512]
    const float* W     = (const float*)d_in[5];  // [4, 512, 512]
    const float* bW    = (const float*)d_in[6];  // [4, 512]
    float* out = (float*)d_out;                  // [2, B, 512]

    int B = in_sizes[0] / 256;

    cudaFuncSetAttribute(lstm_mma_kernel,
                         cudaFuncAttributeMaxDynamicSharedMemorySize, SM_TOTAL);

    lstm_wprep<<<(2048 * 768 + 255) / 256, 256>>>(U, W);
    lstm_zprep<<<(B * 192 + 255) / 256, 256>>>(x, h_old);

    dim3 grid(2048 / BN, B / BM);   // (32, 512) — n fastest for L2 A-stripe reuse
    lstm_mma_kernel<<<grid, NTHR, SM_TOTAL>>>(c_old, bU, bW, out, B);
}